// round 11
// baseline (speedup 1.0000x reference)
#include <cuda_runtime.h>
#include <cuda_fp16.h>
#include <cstdint>

// VectorQuantizer: single-product FP16 mma.sync screen (e pre-scaled x1024) +
// provable-margin exact rescore (warp-parallel, reference chain).
// 1 CTA/SM, full register file. B=32, D=64, T=8192, K=512.

#define BB 32
#define DD 64
#define TT 8192
#define KK 512
#define TILE_M 128
#define NTILES 2048
#define TILES_PER_B 64
#define NTHREADS 256
#define GRIDX 152
#define ARRSZ ((long long)BB * DD * TT)
#define MARGIN 2.5e-4f
#define FINF 3.402823466e38f

#define RSTRIDE 144             // 72 fp16 per row (conflict-free ldmatrix)
#define ESCALE 1024.0f
#define EINV  (-0.001953125f)   // -2/1024, exact
#define XS_STRIDE 65

// smem byte offsets
#define OFF_QN   0
#define OFF_E2   128       // 512 f -> 2176
#define OFF_X2   2176      // 128 f -> 2688
#define OFF_WIN  2688      // 128 i -> 3200
#define OFF_QUE  3200      // 128 i -> 3712
#define OFF_XS   3712      // 128*65*4 = 33280 -> 36992
#define OFF_XH   36992     // 128*144 = 18432 -> 55424
#define OFF_EH   55424     // 512*144 = 73728 -> 129152
#define OFF_QS   129152    // 64*128*4 = 32768 -> 161920
#define SMEM_TOTAL 161920

__device__ __forceinline__ uint32_t smem_u32(const void* p) {
    uint32_t a;
    asm("{ .reg .u64 t; cvta.to.shared.u64 t, %1; cvt.u32.u64 %0, t; }" : "=r"(a) : "l"(p));
    return a;
}
__device__ __forceinline__ void ldsm_x4(uint32_t& r0, uint32_t& r1, uint32_t& r2, uint32_t& r3,
                                        uint32_t addr) {
    asm volatile("ldmatrix.sync.aligned.m8n8.x4.shared.b16 {%0,%1,%2,%3}, [%4];"
                 : "=r"(r0), "=r"(r1), "=r"(r2), "=r"(r3) : "r"(addr));
}
__device__ __forceinline__ void mma_f16(float* c, const uint32_t* a, uint32_t b0, uint32_t b1) {
    asm volatile("mma.sync.aligned.m16n8k16.row.col.f32.f16.f16.f32 "
                 "{%0,%1,%2,%3}, {%4,%5,%6,%7}, {%8,%9}, {%0,%1,%2,%3};"
                 : "+f"(c[0]), "+f"(c[1]), "+f"(c[2]), "+f"(c[3])
                 : "r"(a[0]), "r"(a[1]), "r"(a[2]), "r"(a[3]), "r"(b0), "r"(b1));
}
__device__ __forceinline__ uint32_t pack_h2(float lo, float hi) {
    __half2 h = __floats2half2_rn(lo, hi);
    return *reinterpret_cast<uint32_t*>(&h);
}
__device__ __forceinline__ void top2(float dd, int k, float& d1, float& d2, int& i1) {
    if (dd < d1) { d2 = d1; d1 = dd; i1 = k; }
    else if (dd < d2) { d2 = dd; }
}

extern __shared__ __align__(1024) char smem[];

__global__ void __launch_bounds__(NTHREADS, 1)
vq_f16_kernel(const float* __restrict__ x,
              const float* __restrict__ emb,
              float* __restrict__ out) {
    const int tid  = threadIdx.x;
    const int wid  = tid >> 5;
    const int lane = tid & 31;
    const uint32_t sb = smem_u32(smem);

    float* s_e2  = (float*)(smem + OFF_E2);
    float* s_x2  = (float*)(smem + OFF_X2);
    int*   s_win = (int*)(smem + OFF_WIN);
    int*   s_que = (int*)(smem + OFF_QUE);
    float* s_xs  = (float*)(smem + OFF_XS);
    int*   s_qn  = (int*)(smem + OFF_QN);
    float* q_s   = (float*)(smem + OFF_QS);

    // ---- Prologue: codebook -> exact e2 chain + fp16 rows (e * 1024) ----
    for (int r = tid; r < KK; r += NTHREADS) {
        float ev[DD];
        const float4* er = (const float4*)(emb + r * DD);
        #pragma unroll
        for (int g = 0; g < DD / 4; g++) {
            float4 v = er[g];
            ev[g*4+0] = v.x; ev[g*4+1] = v.y; ev[g*4+2] = v.z; ev[g*4+3] = v.w;
        }
        float s = 0.0f;
        #pragma unroll
        for (int d = 0; d < DD; d++) s = __fadd_rn(s, __fmul_rn(ev[d], ev[d]));
        s_e2[r] = s;
        #pragma unroll
        for (int d = 0; d < DD; d += 2)
            *(uint32_t*)(smem + OFF_EH + r * RSTRIDE + d * 2) =
                pack_h2(ev[d] * ESCALE, ev[d+1] * ESCALE);
    }

    float* o_st = out;
    float* o_q  = out + ARRSZ;

    const int lane4 = lane & 3;
    const int laneg = lane >> 2;
    const uint32_t a_off = (uint32_t)((lane & 15) * RSTRIDE + (lane >> 4) * 16);
    const uint32_t b_off = (uint32_t)((((lane & 7) + ((lane >> 4) << 3)) * RSTRIDE) +
                                      (((lane >> 3) & 1) * 16));

    for (int tile = blockIdx.x; tile < NTILES; tile += GRIDX) {
        const int b  = tile / TILES_PER_B;
        const int t0 = (tile % TILES_PER_B) * TILE_M;
        const float* xb = x + (long long)b * DD * TT + t0;
        const long long obase = (long long)b * DD * TT;

        // ---- Phase A: x load (threads 0..127), stage f32, exact x2, fp16 ----
        if (tid == 0) *s_qn = 0;
        if (tid < TILE_M) {
            const int tt = tid;
            float xv[DD];
            #pragma unroll
            for (int d = 0; d < DD; d++) xv[d] = xb[(long long)d * TT + tt];
            float s = 0.0f;
            #pragma unroll
            for (int d = 0; d < DD; d++) {
                s_xs[tt * XS_STRIDE + d] = xv[d];
                s = __fadd_rn(s, __fmul_rn(xv[d], xv[d]));
            }
            s_x2[tt] = s;
            #pragma unroll
            for (int d = 0; d < DD; d += 2)
                *(uint32_t*)(smem + OFF_XH + tt * RSTRIDE + d * 2) =
                    pack_h2(xv[d], xv[d+1]);
        }
        __syncthreads();

        // ---- Phase B: screen. warp w: tokens [16w,16w+16), all 512 codes ----
        {
            const int m0 = wid * 16;
            uint32_t ah[4][4];
            const uint32_t abh = sb + OFF_XH + m0 * RSTRIDE + a_off;
            #pragma unroll
            for (int s = 0; s < 4; s++)
                ldsm_x4(ah[s][0], ah[s][1], ah[s][2], ah[s][3], abh + s * 32);

            float d1a = FINF, d2a = FINF, d1b = FINF, d2b = FINF;
            int   i1a = 0, i1b = 0;
            const uint32_t bbh = sb + OFF_EH + b_off;

            for (int c = 0; c < 8; c++) {
                const int n0 = c * 64;
                #pragma unroll
                for (int p = 0; p < 4; p++) {
                    float acc0[4] = {0.f, 0.f, 0.f, 0.f};
                    float acc1[4] = {0.f, 0.f, 0.f, 0.f};
                    const uint32_t bt = bbh + (uint32_t)((n0 + 16 * p) * RSTRIDE);
                    #pragma unroll
                    for (int s = 0; s < 4; s++) {
                        uint32_t b0, b1, b2, b3;
                        ldsm_x4(b0, b1, b2, b3, bt + s * 32);
                        mma_f16(acc0, ah[s], b0, b1);
                        mma_f16(acc1, ah[s], b2, b3);
                    }
                    // acc = 1024*xe ; screen dist (x2 dropped): e2 - 2*xe
                    const int cb0 = n0 + 16 * p + 2 * lane4;
                    const int cb1 = cb0 + 8;
                    const float e00 = s_e2[cb0], e01 = s_e2[cb0 + 1];
                    const float e10 = s_e2[cb1], e11 = s_e2[cb1 + 1];
                    float dd;
                    dd = fmaf(EINV, acc0[0], e00); top2(dd, cb0,     d1a, d2a, i1a);
                    dd = fmaf(EINV, acc0[1], e01); top2(dd, cb0 + 1, d1a, d2a, i1a);
                    dd = fmaf(EINV, acc0[2], e00); top2(dd, cb0,     d1b, d2b, i1b);
                    dd = fmaf(EINV, acc0[3], e01); top2(dd, cb0 + 1, d1b, d2b, i1b);
                    dd = fmaf(EINV, acc1[0], e10); top2(dd, cb1,     d1a, d2a, i1a);
                    dd = fmaf(EINV, acc1[1], e11); top2(dd, cb1 + 1, d1a, d2a, i1a);
                    dd = fmaf(EINV, acc1[2], e10); top2(dd, cb1,     d1b, d2b, i1b);
                    dd = fmaf(EINV, acc1[3], e11); top2(dd, cb1 + 1, d1b, d2b, i1b);
                }
            }

            // quad reduce (lanes xor 1, 2) lexicographic (d, k)
            #pragma unroll
            for (int m = 1; m <= 2; m <<= 1) {
                float od = __shfl_xor_sync(0xffffffffu, d1a, m);
                int   oi = __shfl_xor_sync(0xffffffffu, i1a, m);
                float o2 = __shfl_xor_sync(0xffffffffu, d2a, m);
                bool take = (od < d1a) || (od == d1a && oi < i1a);
                float nd2 = take ? fminf(d1a, o2) : fminf(d2a, od);
                if (take) { d1a = od; i1a = oi; }
                d2a = nd2;
                od = __shfl_xor_sync(0xffffffffu, d1b, m);
                oi = __shfl_xor_sync(0xffffffffu, i1b, m);
                o2 = __shfl_xor_sync(0xffffffffu, d2b, m);
                take = (od < d1b) || (od == d1b && oi < i1b);
                nd2 = take ? fminf(d1b, o2) : fminf(d2b, od);
                if (take) { d1b = od; i1b = oi; }
                d2b = nd2;
            }
            if (lane4 == 0) {
                const int r0 = m0 + laneg, r1 = r0 + 8;
                s_win[r0] = i1a;
                if (!(d2a - d1a > MARGIN)) { int q = atomicAdd(s_qn, 1); s_que[q] = r0; }
                s_win[r1] = i1b;
                if (!(d2b - d1b > MARGIN)) { int q = atomicAdd(s_qn, 1); s_que[q] = r1; }
            }
        }
        __syncthreads();

        // ---- Phase E: warp-parallel exact rescore (reference chain) ----
        {
            const int nq = *s_qn;
            for (int j = wid; j < nq; j += 8) {
                const int tt = s_que[j];
                const float x2t = s_x2[tt];
                // lane owns codes [lane*16, lane*16+16); chunked dot (16 dims)
                float ps[16];
                #pragma unroll
                for (int kk = 0; kk < 16; kk++) ps[kk] = 0.0f;
                #pragma unroll 1
                for (int ch = 0; ch < 4; ch++) {
                    float xr[16];
                    #pragma unroll
                    for (int d = 0; d < 16; d++)
                        xr[d] = s_xs[tt * XS_STRIDE + ch * 16 + d];
                    #pragma unroll 1
                    for (int kk = 0; kk < 16; kk++) {
                        const float4* e0 =
                            (const float4*)(emb + (lane * 16 + kk) * DD + ch * 16);
                        float s0 = ps[kk];
                        #pragma unroll
                        for (int g = 0; g < 4; g++) {
                            float4 v = __ldg(e0 + g);
                            s0 = fmaf(xr[g*4+0], v.x, s0);
                            s0 = fmaf(xr[g*4+1], v.y, s0);
                            s0 = fmaf(xr[g*4+2], v.z, s0);
                            s0 = fmaf(xr[g*4+3], v.w, s0);
                        }
                        ps[kk] = s0;
                    }
                }
                float bd = FINF; int bk = 0;
                #pragma unroll
                for (int kk = 0; kk < 16; kk++) {
                    const int k = lane * 16 + kk;
                    float dA = __fadd_rn(__fsub_rn(x2t, 2.0f * ps[kk]), s_e2[k]);
                    if (dA < bd) { bd = dA; bk = k; }
                }
                #pragma unroll
                for (int off = 16; off; off >>= 1) {
                    float od = __shfl_down_sync(0xFFFFFFFFu, bd, off);
                    int   ok = __shfl_down_sync(0xFFFFFFFFu, bk, off);
                    if (od < bd || (od == bd && ok < bk)) { bd = od; bk = ok; }
                }
                if (lane == 0) s_win[tt] = bk;
            }
        }
        __syncthreads();

        // ---- Phase F: gather q rows to smem, then coalesced writes ----
        if (tid < TILE_M) {
            const int tt = tid;
            const int k = s_win[tt];
            const float4* er = (const float4*)(emb + k * DD);
            #pragma unroll
            for (int g = 0; g < DD / 4; g++) {
                float4 v = __ldg(er + g);
                q_s[(g*4+0) * 128 + tt] = v.x;
                q_s[(g*4+1) * 128 + tt] = v.y;
                q_s[(g*4+2) * 128 + tt] = v.z;
                q_s[(g*4+3) * 128 + tt] = v.w;
            }
        }
        __syncthreads();
        {
            #pragma unroll
            for (int it = 0; it < (64 * 64) / NTHREADS; it++) {
                const int item = tid + it * NTHREADS;
                const int d = item >> 6;
                const int p = item & 63;
                const int ti = p * 2;
                float q0 = q_s[d * 128 + ti];
                float q1 = q_s[d * 128 + ti + 1];
                float x0 = s_xs[ti * XS_STRIDE + d];
                float x1 = s_xs[(ti + 1) * XS_STRIDE + d];
                float2 stv = make_float2(__fadd_rn(x0, __fsub_rn(q0, x0)),
                                         __fadd_rn(x1, __fsub_rn(q1, x1)));
                float2 qv = make_float2(q0, q1);
                const long long o = obase + (long long)d * TT + t0 + ti;
                *(float2*)(o_st + o) = stv;
                *(float2*)(o_q + o)  = qv;
            }
        }
        __syncthreads();
    }
}

extern "C" void kernel_launch(void* const* d_in, const int* in_sizes, int n_in,
                              void* d_out, int out_size) {
    const float* x   = (const float*)d_in[0];
    const float* emb = (const float*)d_in[1];
    float* out = (float*)d_out;
    (void)in_sizes; (void)n_in; (void)out_size;

    cudaFuncSetAttribute(vq_f16_kernel,
                         cudaFuncAttributeMaxDynamicSharedMemorySize, SMEM_TOTAL);
    vq_f16_kernel<<<GRIDX, NTHREADS, SMEM_TOTAL>>>(x, emb, out);
}

// round 13
// speedup vs baseline: 1.6405x; 1.6405x over previous
#include <cuda_runtime.h>
#include <cuda_fp16.h>
#include <cstdint>

// VectorQuantizer: single-product FP16 mma.sync screen (e pre-scaled x1024) +
// provable-margin exact rescore from SMEM f32 codebook (warp-parallel).
// 1 CTA/SM. B=32, D=64, T=8192, K=512.

#define BB 32
#define DD 64
#define TT 8192
#define KK 512
#define TILE_M 128
#define NTILES 2048
#define TILES_PER_B 64
#define NTHREADS 256
#define GRIDX 152
#define ARRSZ ((long long)BB * DD * TT)
#define MARGIN 2.5e-4f
#define FINF 3.402823466e38f

#define RSTRIDE 144             // 72 fp16 per row (conflict-free ldmatrix)
#define ESCALE 1024.0f
#define EINV  (-0.001953125f)   // -2/1024, exact
#define EFS 66                  // f32 codebook row stride (words); rows 8B-aligned

// smem byte offsets
#define OFF_QN   0
#define OFF_E2   128       // 512 f -> 2176
#define OFF_X2   2176      // 128 f -> 2688
#define OFF_WIN  2688      // 128 i -> 3200
#define OFF_QUE  3200      // 128 i -> 3712
#define OFF_XH   3840      // 128*144 = 18432 -> 22272
#define OFF_EH   22272     // 512*144 = 73728 -> 96000
#define OFF_EF   96000     // 512*66*4 = 135168 -> 231168
#define SMEM_TOTAL 231168

__device__ __forceinline__ uint32_t smem_u32(const void* p) {
    uint32_t a;
    asm("{ .reg .u64 t; cvta.to.shared.u64 t, %1; cvt.u32.u64 %0, t; }" : "=r"(a) : "l"(p));
    return a;
}
__device__ __forceinline__ void ldsm_x4(uint32_t& r0, uint32_t& r1, uint32_t& r2, uint32_t& r3,
                                        uint32_t addr) {
    asm volatile("ldmatrix.sync.aligned.m8n8.x4.shared.b16 {%0,%1,%2,%3}, [%4];"
                 : "=r"(r0), "=r"(r1), "=r"(r2), "=r"(r3) : "r"(addr));
}
__device__ __forceinline__ void mma_f16(float* c, const uint32_t* a, uint32_t b0, uint32_t b1) {
    asm volatile("mma.sync.aligned.m16n8k16.row.col.f32.f16.f16.f32 "
                 "{%0,%1,%2,%3}, {%4,%5,%6,%7}, {%8,%9}, {%0,%1,%2,%3};"
                 : "+f"(c[0]), "+f"(c[1]), "+f"(c[2]), "+f"(c[3])
                 : "r"(a[0]), "r"(a[1]), "r"(a[2]), "r"(a[3]), "r"(b0), "r"(b1));
}
__device__ __forceinline__ uint32_t pack_h2(float lo, float hi) {
    __half2 h = __floats2half2_rn(lo, hi);
    return *reinterpret_cast<uint32_t*>(&h);
}
__device__ __forceinline__ void top2(float dd, int k, float& d1, float& d2, int& i1) {
    if (dd < d1) { d2 = d1; d1 = dd; i1 = k; }
    else if (dd < d2) { d2 = dd; }
}

extern __shared__ __align__(1024) char smem[];

__global__ void __launch_bounds__(NTHREADS, 1)
vq_f16_kernel(const float* __restrict__ x,
              const float* __restrict__ emb,
              float* __restrict__ out) {
    const int tid  = threadIdx.x;
    const int wid  = tid >> 5;
    const int lane = tid & 31;
    const uint32_t sb = smem_u32(smem);

    float* s_e2  = (float*)(smem + OFF_E2);
    float* s_x2  = (float*)(smem + OFF_X2);
    int*   s_win = (int*)(smem + OFF_WIN);
    int*   s_que = (int*)(smem + OFF_QUE);
    int*   s_qn  = (int*)(smem + OFF_QN);
    float* s_ef  = (float*)(smem + OFF_EF);

    // ---- Prologue: codebook -> exact e2 chain + fp16 rows (e*1024) + f32 copy ----
    for (int r = tid; r < KK; r += NTHREADS) {
        float ev[DD];
        const float4* er = (const float4*)(emb + r * DD);
        #pragma unroll
        for (int g = 0; g < DD / 4; g++) {
            float4 v = er[g];
            ev[g*4+0] = v.x; ev[g*4+1] = v.y; ev[g*4+2] = v.z; ev[g*4+3] = v.w;
        }
        float s = 0.0f;
        #pragma unroll
        for (int d = 0; d < DD; d++) s = __fadd_rn(s, __fmul_rn(ev[d], ev[d]));
        s_e2[r] = s;
        #pragma unroll
        for (int d = 0; d < DD; d += 2)
            *(uint32_t*)(smem + OFF_EH + r * RSTRIDE + d * 2) =
                pack_h2(ev[d] * ESCALE, ev[d+1] * ESCALE);
        #pragma unroll
        for (int d = 0; d < DD; d++) s_ef[r * EFS + d] = ev[d];
    }

    float* o_st = out;
    float* o_q  = out + ARRSZ;

    const int lane4 = lane & 3;
    const int laneg = lane >> 2;
    const uint32_t a_off = (uint32_t)((lane & 15) * RSTRIDE + (lane >> 4) * 16);
    const uint32_t b_off = (uint32_t)((((lane & 7) + ((lane >> 4) << 3)) * RSTRIDE) +
                                      (((lane >> 3) & 1) * 16));

    for (int tile = blockIdx.x; tile < NTILES; tile += GRIDX) {
        const int b  = tile / TILES_PER_B;
        const int t0 = (tile % TILES_PER_B) * TILE_M;
        const float* xb = x + (long long)b * DD * TT + t0;
        const long long obase = (long long)b * DD * TT;

        // ---- Phase A: x load (threads 0..127), exact x2 chain, fp16 rows ----
        if (tid == 0) *s_qn = 0;
        if (tid < TILE_M) {
            const int tt = tid;
            float xv[DD];
            #pragma unroll
            for (int d = 0; d < DD; d++) xv[d] = xb[(long long)d * TT + tt];
            float s = 0.0f;
            #pragma unroll
            for (int d = 0; d < DD; d++) s = __fadd_rn(s, __fmul_rn(xv[d], xv[d]));
            s_x2[tt] = s;
            #pragma unroll
            for (int d = 0; d < DD; d += 2)
                *(uint32_t*)(smem + OFF_XH + tt * RSTRIDE + d * 2) =
                    pack_h2(xv[d], xv[d+1]);
        }
        __syncthreads();

        // ---- Phase B: screen. warp w: tokens [16w,16w+16), all 512 codes ----
        {
            const int m0 = wid * 16;
            uint32_t ah[4][4];
            const uint32_t abh = sb + OFF_XH + m0 * RSTRIDE + a_off;
            #pragma unroll
            for (int s = 0; s < 4; s++)
                ldsm_x4(ah[s][0], ah[s][1], ah[s][2], ah[s][3], abh + s * 32);

            // two tracker sets per row-half (p parity) to halve carried chains
            float d1a[2] = {FINF, FINF}, d2a[2] = {FINF, FINF};
            float d1b[2] = {FINF, FINF}, d2b[2] = {FINF, FINF};
            int   i1a[2] = {0, 0}, i1b[2] = {0, 0};
            const uint32_t bbh = sb + OFF_EH + b_off;

            for (int c = 0; c < 8; c++) {
                const int n0 = c * 64;
                #pragma unroll
                for (int p = 0; p < 4; p++) {
                    const int q = p & 1;
                    float acc0[4] = {0.f, 0.f, 0.f, 0.f};
                    float acc1[4] = {0.f, 0.f, 0.f, 0.f};
                    const uint32_t bt = bbh + (uint32_t)((n0 + 16 * p) * RSTRIDE);
                    #pragma unroll
                    for (int s = 0; s < 4; s++) {
                        uint32_t b0, b1, b2, b3;
                        ldsm_x4(b0, b1, b2, b3, bt + s * 32);
                        mma_f16(acc0, ah[s], b0, b1);
                        mma_f16(acc1, ah[s], b2, b3);
                    }
                    // acc = 1024*xe ; screen dist (x2 dropped): e2 - 2*xe
                    const int cb0 = n0 + 16 * p + 2 * lane4;
                    const int cb1 = cb0 + 8;
                    const float e00 = s_e2[cb0], e01 = s_e2[cb0 + 1];
                    const float e10 = s_e2[cb1], e11 = s_e2[cb1 + 1];
                    float dd;
                    dd = fmaf(EINV, acc0[0], e00); top2(dd, cb0,     d1a[q], d2a[q], i1a[q]);
                    dd = fmaf(EINV, acc0[1], e01); top2(dd, cb0 + 1, d1a[q], d2a[q], i1a[q]);
                    dd = fmaf(EINV, acc0[2], e00); top2(dd, cb0,     d1b[q], d2b[q], i1b[q]);
                    dd = fmaf(EINV, acc0[3], e01); top2(dd, cb0 + 1, d1b[q], d2b[q], i1b[q]);
                    dd = fmaf(EINV, acc1[0], e10); top2(dd, cb1,     d1a[q], d2a[q], i1a[q]);
                    dd = fmaf(EINV, acc1[1], e11); top2(dd, cb1 + 1, d1a[q], d2a[q], i1a[q]);
                    dd = fmaf(EINV, acc1[2], e10); top2(dd, cb1,     d1b[q], d2b[q], i1b[q]);
                    dd = fmaf(EINV, acc1[3], e11); top2(dd, cb1 + 1, d1b[q], d2b[q], i1b[q]);
                }
            }

            // merge parity sets (lexicographic on (d, k))
            float D1a, D2a, D1b, D2b; int I1a, I1b;
            {
                bool t = (d1a[1] < d1a[0]) || (d1a[1] == d1a[0] && i1a[1] < i1a[0]);
                D1a = t ? d1a[1] : d1a[0];
                I1a = t ? i1a[1] : i1a[0];
                D2a = t ? fminf(d1a[0], d2a[1]) : fminf(d2a[0], d1a[1]);
                t = (d1b[1] < d1b[0]) || (d1b[1] == d1b[0] && i1b[1] < i1b[0]);
                D1b = t ? d1b[1] : d1b[0];
                I1b = t ? i1b[1] : i1b[0];
                D2b = t ? fminf(d1b[0], d2b[1]) : fminf(d2b[0], d1b[1]);
            }

            // quad reduce (lanes xor 1, 2) lexicographic (d, k)
            #pragma unroll
            for (int m = 1; m <= 2; m <<= 1) {
                float od = __shfl_xor_sync(0xffffffffu, D1a, m);
                int   oi = __shfl_xor_sync(0xffffffffu, I1a, m);
                float o2 = __shfl_xor_sync(0xffffffffu, D2a, m);
                bool take = (od < D1a) || (od == D1a && oi < I1a);
                float nd2 = take ? fminf(D1a, o2) : fminf(D2a, od);
                if (take) { D1a = od; I1a = oi; }
                D2a = nd2;
                od = __shfl_xor_sync(0xffffffffu, D1b, m);
                oi = __shfl_xor_sync(0xffffffffu, I1b, m);
                o2 = __shfl_xor_sync(0xffffffffu, D2b, m);
                take = (od < D1b) || (od == D1b && oi < I1b);
                nd2 = take ? fminf(D1b, o2) : fminf(D2b, od);
                if (take) { D1b = od; I1b = oi; }
                D2b = nd2;
            }
            if (lane4 == 0) {
                const int r0 = m0 + laneg, r1 = r0 + 8;
                s_win[r0] = I1a;
                if (!(D2a - D1a > MARGIN)) { int q = atomicAdd(s_qn, 1); s_que[q] = r0; }
                s_win[r1] = I1b;
                if (!(D2b - D1b > MARGIN)) { int q = atomicAdd(s_qn, 1); s_que[q] = r1; }
            }
        }
        __syncthreads();

        // ---- Phase E: warp-parallel exact rescore from SMEM f32 codebook ----
        {
            const int nq = *s_qn;
            for (int j = wid; j < nq; j += 8) {
                const int tt = s_que[j];
                const float x2t = s_x2[tt];
                float bd = FINF; int bk = 0;
                float ps[16];
                #pragma unroll
                for (int kk = 0; kk < 16; kk++) ps[kk] = 0.0f;
                #pragma unroll 1
                for (int ch = 0; ch < 4; ch++) {
                    float xr[16];
                    #pragma unroll
                    for (int d = 0; d < 16; d++)
                        xr[d] = __ldg(xb + (long long)(ch * 16 + d) * TT + tt);
                    #pragma unroll 1
                    for (int kk = 0; kk < 16; kk++) {
                        // lane owns codes {32*kk + lane}, ascending kk
                        // rows are 8B-aligned (EFS=66) -> float2 loads
                        const float2* e0 =
                            (const float2*)(s_ef + (kk * 32 + lane) * EFS + ch * 16);
                        float s0 = ps[kk];
                        #pragma unroll
                        for (int g = 0; g < 8; g++) {
                            float2 v = e0[g];
                            s0 = fmaf(xr[g*2+0], v.x, s0);
                            s0 = fmaf(xr[g*2+1], v.y, s0);
                        }
                        ps[kk] = s0;
                    }
                }
                #pragma unroll
                for (int kk = 0; kk < 16; kk++) {
                    const int k = kk * 32 + lane;
                    float dA = __fadd_rn(__fsub_rn(x2t, 2.0f * ps[kk]), s_e2[k]);
                    if (dA < bd) { bd = dA; bk = k; }
                }
                #pragma unroll
                for (int off = 16; off; off >>= 1) {
                    float od = __shfl_down_sync(0xFFFFFFFFu, bd, off);
                    int   ok = __shfl_down_sync(0xFFFFFFFFu, bk, off);
                    if (od < bd || (od == bd && ok < bk)) { bd = od; bk = ok; }
                }
                if (lane == 0) s_win[tt] = bk;
            }
        }
        __syncthreads();

        // ---- Phase F: outputs direct from SMEM codebook + gmem x ----
        {
            const int pr = tid & 63;          // token pair (2pr, 2pr+1)
            const int qd = tid >> 6;          // d quarter [16qd, 16qd+16)
            const int ta = 2 * pr;
            const int ka = s_win[ta], kb = s_win[ta + 1];
            const float* ea = s_ef + ka * EFS + qd * 16;
            const float* eb = s_ef + kb * EFS + qd * 16;
            #pragma unroll
            for (int i = 0; i < 16; i++) {
                const int d = qd * 16 + i;
                const float qa = ea[i];
                const float qb = eb[i];
                const float2 xv = *(const float2*)(xb + (long long)d * TT + ta);
                float2 stv = make_float2(__fadd_rn(xv.x, __fsub_rn(qa, xv.x)),
                                         __fadd_rn(xv.y, __fsub_rn(qb, xv.y)));
                float2 qv = make_float2(qa, qb);
                const long long o = obase + (long long)d * TT + t0 + ta;
                *(float2*)(o_st + o) = stv;
                *(float2*)(o_q + o)  = qv;
            }
        }
        __syncthreads();
    }
}

extern "C" void kernel_launch(void* const* d_in, const int* in_sizes, int n_in,
                              void* d_out, int out_size) {
    const float* x   = (const float*)d_in[0];
    const float* emb = (const float*)d_in[1];
    float* out = (float*)d_out;
    (void)in_sizes; (void)n_in; (void)out_size;

    cudaFuncSetAttribute(vq_f16_kernel,
                         cudaFuncAttributeMaxDynamicSharedMemorySize, SMEM_TOTAL);
    vq_f16_kernel<<<GRIDX, NTHREADS, SMEM_TOTAL>>>(x, emb, out);
}

// round 14
// speedup vs baseline: 1.6661x; 1.0156x over previous
#include <cuda_runtime.h>
#include <cuda_bf16.h>
#include <cstdint>

// VectorQuantizer via mma.sync (HMMA bf16, split-precision) + exact-margin rescore.
// R14 = R5 + coalesced warp-per-token rescore from a transposed codebook in a
// __device__ global (fills via a tiny pre-kernel). B=32, D=64, T=8192, K=512.

#define BB 32
#define DD 64
#define TT 8192
#define KK 512
#define NTOK (BB * TT)
#define TILE_M 128
#define NTILES (NTOK / TILE_M)      // 2048
#define TILES_PER_B (TT / TILE_M)   // 64
#define NTHREADS 256
#define GRIDX 152
#define ARRSZ ((long long)BB * DD * TT)
#define MARGIN 5e-5f
#define FINF 3.402823466e38f

// bf16 row stride: 72 elems = 144 bytes (conflict-free ldmatrix)
#define ROWS72 72
#define RSTRIDE (ROWS72 * 2)

// smem byte offsets
#define OFF_QN     0
#define OFF_E2     128      // 512 f -> 2176
#define OFF_X2     2176     // 128 f -> 2688
#define OFF_WIN    2688     // 128 i -> 3200
#define OFF_QUE    3200     // 128 i -> 3712
#define OFF_XS     3712     // 128*65*4 = 33280 -> 36992
#define OFF_XH     36992    // 128*144 = 18432 -> 55424
#define OFF_XL     55424    // 18432 -> 73856
#define OFF_QS     OFF_XH   // overlay: 64*128*4 = 32768 <= 36864 (XH+XL)
#define OFF_EH     73856    // 512*144 = 73728 -> 147584
#define OFF_EL     147584   // 73728 -> 221312
#define SMEM_TOTAL 221312
#define XS_STRIDE  65

// transposed f32 codebook: embT[d][k]
__device__ __align__(16) float g_embT[DD * KK];

__global__ void vq_transpose_kernel(const float* __restrict__ emb) {
    const int idx = blockIdx.x * blockDim.x + threadIdx.x;
    if (idx < KK * DD) {
        const int k = idx / DD;
        const int d = idx % DD;
        g_embT[d * KK + k] = emb[idx];
    }
}

__device__ __forceinline__ uint32_t smem_u32(const void* p) {
    uint32_t a;
    asm("{ .reg .u64 t; cvta.to.shared.u64 t, %1; cvt.u32.u64 %0, t; }" : "=r"(a) : "l"(p));
    return a;
}
__device__ __forceinline__ void ldsm_x4(uint32_t& r0, uint32_t& r1, uint32_t& r2, uint32_t& r3,
                                        uint32_t addr) {
    asm volatile("ldmatrix.sync.aligned.m8n8.x4.shared.b16 {%0,%1,%2,%3}, [%4];"
                 : "=r"(r0), "=r"(r1), "=r"(r2), "=r"(r3) : "r"(addr));
}
__device__ __forceinline__ void mma_bf16(float* c, const uint32_t* a, uint32_t b0, uint32_t b1) {
    asm volatile("mma.sync.aligned.m16n8k16.row.col.f32.bf16.bf16.f32 "
                 "{%0,%1,%2,%3}, {%4,%5,%6,%7}, {%8,%9}, {%0,%1,%2,%3};"
                 : "+f"(c[0]), "+f"(c[1]), "+f"(c[2]), "+f"(c[3])
                 : "r"(a[0]), "r"(a[1]), "r"(a[2]), "r"(a[3]), "r"(b0), "r"(b1));
}
__device__ __forceinline__ uint32_t pack_hi2(float v0, float v1, float& r0, float& r1) {
    __nv_bfloat16 h0 = __float2bfloat16_rn(v0);
    __nv_bfloat16 h1 = __float2bfloat16_rn(v1);
    r0 = __fsub_rn(v0, __bfloat162float(h0));
    r1 = __fsub_rn(v1, __bfloat162float(h1));
    return (uint32_t)__bfloat16_as_ushort(h0) | ((uint32_t)__bfloat16_as_ushort(h1) << 16);
}
__device__ __forceinline__ uint32_t pack_lo2(float r0, float r1) {
    __nv_bfloat16 l0 = __float2bfloat16_rn(r0);
    __nv_bfloat16 l1 = __float2bfloat16_rn(r1);
    return (uint32_t)__bfloat16_as_ushort(l0) | ((uint32_t)__bfloat16_as_ushort(l1) << 16);
}
__device__ __forceinline__ void top2(float dd, int k, float& d1, float& d2, int& i1) {
    if (dd < d1) { d2 = d1; d1 = dd; i1 = k; }
    else if (dd < d2) { d2 = dd; }
}

extern __shared__ __align__(1024) char smem[];

__global__ void __launch_bounds__(NTHREADS, 1)
vq_mma_kernel(const float* __restrict__ x,
              const float* __restrict__ emb,
              float* __restrict__ out) {
    const int tid  = threadIdx.x;
    const int wid  = tid >> 5;
    const int lane = tid & 31;
    const uint32_t sb = smem_u32(smem);

    float* s_e2   = (float*)(smem + OFF_E2);
    float* s_x2   = (float*)(smem + OFF_X2);
    int*   s_win  = (int*)(smem + OFF_WIN);
    int*   s_que  = (int*)(smem + OFF_QUE);
    float* s_xs   = (float*)(smem + OFF_XS);
    int*   s_qn   = (int*)(smem + OFF_QN);
    float* q_s    = (float*)(smem + OFF_QS);

    // ---- Prologue: codebook -> exact e2 chain + bf16 split rows [512][72] ----
    for (int r = tid; r < KK; r += NTHREADS) {
        float ev[DD];
        const float4* er = (const float4*)(emb + r * DD);
        #pragma unroll
        for (int g = 0; g < DD / 4; g++) {
            float4 v = er[g];
            ev[g*4+0] = v.x; ev[g*4+1] = v.y; ev[g*4+2] = v.z; ev[g*4+3] = v.w;
        }
        float s = 0.0f;
        #pragma unroll
        for (int d = 0; d < DD; d++) s = __fadd_rn(s, __fmul_rn(ev[d], ev[d]));
        s_e2[r] = s;
        #pragma unroll
        for (int d = 0; d < DD; d += 2) {
            float r0, r1;
            uint32_t hp = pack_hi2(ev[d], ev[d+1], r0, r1);
            uint32_t lp = pack_lo2(r0, r1);
            *(uint32_t*)(smem + OFF_EH + r * RSTRIDE + d * 2) = hp;
            *(uint32_t*)(smem + OFF_EL + r * RSTRIDE + d * 2) = lp;
        }
    }

    float* o_st = out;
    float* o_q  = out + ARRSZ;

    const int lane4 = lane & 3;
    const int laneg = lane >> 2;
    const uint32_t a_off = (uint32_t)((lane & 15) * RSTRIDE + (lane >> 4) * 16);
    const uint32_t b_off = (uint32_t)((((lane & 7) + ((lane >> 4) << 3)) * RSTRIDE) +
                                      (((lane >> 3) & 1) * 16));

    for (int tile = blockIdx.x; tile < NTILES; tile += GRIDX) {
        const int b  = tile / TILES_PER_B;
        const int t0 = (tile % TILES_PER_B) * TILE_M;
        const float* xb = x + (long long)b * DD * TT + t0;
        const long long obase = (long long)b * DD * TT;

        // ---- Phase A: load x, stage f32, exact x2 chain, bf16 split rows ----
        if (tid == 0) *s_qn = 0;
        if (tid < TILE_M) {
            const int tt = tid;
            float xv[DD];
            #pragma unroll
            for (int d = 0; d < DD; d++) xv[d] = xb[(long long)d * TT + tt];
            float s = 0.0f;
            #pragma unroll
            for (int d = 0; d < DD; d++) {
                s_xs[tt * XS_STRIDE + d] = xv[d];
                s = __fadd_rn(s, __fmul_rn(xv[d], xv[d]));
            }
            s_x2[tt] = s;
            #pragma unroll
            for (int d = 0; d < DD; d += 2) {
                float r0, r1;
                uint32_t hp = pack_hi2(xv[d], xv[d+1], r0, r1);
                uint32_t lp = pack_lo2(r0, r1);
                *(uint32_t*)(smem + OFF_XH + tt * RSTRIDE + d * 2) = hp;
                *(uint32_t*)(smem + OFF_XL + tt * RSTRIDE + d * 2) = lp;
            }
        }
        __syncthreads();

        // ---- Phase B: screen. warp w: tokens [16w,16w+16), all 512 codes ----
        {
            const int m0 = wid * 16;
            uint32_t ah[4][4], al[4][4];
            const uint32_t abh = sb + OFF_XH + m0 * RSTRIDE + a_off;
            const uint32_t abl = sb + OFF_XL + m0 * RSTRIDE + a_off;
            #pragma unroll
            for (int s = 0; s < 4; s++) {
                ldsm_x4(ah[s][0], ah[s][1], ah[s][2], ah[s][3], abh + s * 32);
                ldsm_x4(al[s][0], al[s][1], al[s][2], al[s][3], abl + s * 32);
            }

            float d1a = FINF, d2a = FINF, d1b = FINF, d2b = FINF;
            int   i1a = 0, i1b = 0;
            const uint32_t bbh = sb + OFF_EH + b_off;
            const uint32_t bbl = sb + OFF_EL + b_off;

            for (int c = 0; c < 8; c++) {
                const int n0 = c * 64;
                #pragma unroll
                for (int p = 0; p < 4; p++) {
                    float a0[8], a1[8];
                    #pragma unroll
                    for (int j = 0; j < 8; j++) { a0[j] = 0.f; a1[j] = 0.f; }
                    const uint32_t bth = bbh + (uint32_t)((n0 + 16 * p) * RSTRIDE);
                    const uint32_t btl = bbl + (uint32_t)((n0 + 16 * p) * RSTRIDE);
                    #pragma unroll
                    for (int s = 0; s < 4; s++) {
                        uint32_t h0, h1, h2, h3, l0, l1, l2, l3;
                        ldsm_x4(h0, h1, h2, h3, bth + s * 32);
                        ldsm_x4(l0, l1, l2, l3, btl + s * 32);
                        mma_bf16(a0,     ah[s], h0, h1);   // hh
                        mma_bf16(a0 + 4, ah[s], h2, h3);
                        mma_bf16(a1,     ah[s], l0, l1);   // hl
                        mma_bf16(a1 + 4, ah[s], l2, l3);
                        mma_bf16(a1,     al[s], h0, h1);   // lh
                        mma_bf16(a1 + 4, al[s], h2, h3);
                    }
                    const int cb0 = n0 + 16 * p + 2 * lane4;
                    const int cb1 = cb0 + 8;
                    const float e00 = s_e2[cb0], e01 = s_e2[cb0 + 1];
                    const float e10 = s_e2[cb1], e11 = s_e2[cb1 + 1];
                    float v;
                    v = __fadd_rn(a0[0], a1[0]);
                    top2(fmaf(-2.0f, v, e00), cb0,     d1a, d2a, i1a);
                    v = __fadd_rn(a0[1], a1[1]);
                    top2(fmaf(-2.0f, v, e01), cb0 + 1, d1a, d2a, i1a);
                    v = __fadd_rn(a0[2], a1[2]);
                    top2(fmaf(-2.0f, v, e00), cb0,     d1b, d2b, i1b);
                    v = __fadd_rn(a0[3], a1[3]);
                    top2(fmaf(-2.0f, v, e01), cb0 + 1, d1b, d2b, i1b);
                    v = __fadd_rn(a0[4], a1[4]);
                    top2(fmaf(-2.0f, v, e10), cb1,     d1a, d2a, i1a);
                    v = __fadd_rn(a0[5], a1[5]);
                    top2(fmaf(-2.0f, v, e11), cb1 + 1, d1a, d2a, i1a);
                    v = __fadd_rn(a0[6], a1[6]);
                    top2(fmaf(-2.0f, v, e10), cb1,     d1b, d2b, i1b);
                    v = __fadd_rn(a0[7], a1[7]);
                    top2(fmaf(-2.0f, v, e11), cb1 + 1, d1b, d2b, i1b);
                }
            }

            // quad reduce (lanes xor 1, 2) lexicographic (d, k)
            #pragma unroll
            for (int m = 1; m <= 2; m <<= 1) {
                float od = __shfl_xor_sync(0xffffffffu, d1a, m);
                int   oi = __shfl_xor_sync(0xffffffffu, i1a, m);
                float o2 = __shfl_xor_sync(0xffffffffu, d2a, m);
                bool take = (od < d1a) || (od == d1a && oi < i1a);
                float nd2 = take ? fminf(d1a, o2) : fminf(d2a, od);
                if (take) { d1a = od; i1a = oi; }
                d2a = nd2;
                od = __shfl_xor_sync(0xffffffffu, d1b, m);
                oi = __shfl_xor_sync(0xffffffffu, i1b, m);
                o2 = __shfl_xor_sync(0xffffffffu, d2b, m);
                take = (od < d1b) || (od == d1b && oi < i1b);
                nd2 = take ? fminf(d1b, o2) : fminf(d2b, od);
                if (take) { d1b = od; i1b = oi; }
                d2b = nd2;
            }
            if (lane4 == 0) {
                const int r0 = m0 + laneg, r1 = r0 + 8;
                s_win[r0] = i1a;
                if (!(d2a - d1a > MARGIN)) { int q = atomicAdd(s_qn, 1); s_que[q] = r0; }
                s_win[r1] = i1b;
                if (!(d2b - d1b > MARGIN)) { int q = atomicAdd(s_qn, 1); s_que[q] = r1; }
            }
        }
        __syncthreads();

        // ---- Phase E: warp-per-token exact rescore, COALESCED via g_embT ----
        // lane owns codes {q*128 + lane*4 + j}; fmaf chain ascending d per code
        // (byte-identical to the reference chain), lexicographic (d,k) reduce.
        {
            const int nq = *s_qn;
            for (int j = wid; j < nq; j += 8) {
                const int tt = s_que[j];
                const float x2t = s_x2[tt];
                float ps[16];
                #pragma unroll
                for (int i = 0; i < 16; i++) ps[i] = 0.0f;
                #pragma unroll 1
                for (int d = 0; d < DD; d++) {
                    const float xd = s_xs[tt * XS_STRIDE + d];
                    const float4* row = (const float4*)(g_embT + d * KK);
                    #pragma unroll
                    for (int q = 0; q < 4; q++) {
                        float4 v = __ldg(row + (q * 32 + lane));
                        ps[q*4+0] = fmaf(xd, v.x, ps[q*4+0]);
                        ps[q*4+1] = fmaf(xd, v.y, ps[q*4+1]);
                        ps[q*4+2] = fmaf(xd, v.z, ps[q*4+2]);
                        ps[q*4+3] = fmaf(xd, v.w, ps[q*4+3]);
                    }
                }
                float bd = FINF; int bk = 0;
                #pragma unroll
                for (int q = 0; q < 4; q++) {
                    #pragma unroll
                    for (int jj = 0; jj < 4; jj++) {
                        const int k = q * 128 + lane * 4 + jj;   // ascending per lane
                        float dA = __fadd_rn(__fsub_rn(x2t, 2.0f * ps[q*4+jj]), s_e2[k]);
                        if (dA < bd) { bd = dA; bk = k; }
                    }
                }
                #pragma unroll
                for (int off = 16; off; off >>= 1) {
                    float od = __shfl_down_sync(0xFFFFFFFFu, bd, off);
                    int   ok = __shfl_down_sync(0xFFFFFFFFu, bk, off);
                    if (od < bd || (od == bd && ok < bk)) { bd = od; bk = ok; }
                }
                if (lane == 0) s_win[tt] = bk;
            }
        }
        __syncthreads();

        // ---- Phase F: gather q rows (overlay XH/XL) then coalesced writes ----
        if (tid < TILE_M) {
            const int tt = tid;
            const int k = s_win[tt];
            const float4* er = (const float4*)(emb + k * DD);
            #pragma unroll
            for (int g = 0; g < DD / 4; g++) {
                float4 v = __ldg(er + g);
                q_s[(g*4+0) * 128 + tt] = v.x;
                q_s[(g*4+1) * 128 + tt] = v.y;
                q_s[(g*4+2) * 128 + tt] = v.z;
                q_s[(g*4+3) * 128 + tt] = v.w;
            }
        }
        __syncthreads();
        {
            #pragma unroll
            for (int it = 0; it < (64 * 64) / NTHREADS; it++) {
                const int item = tid + it * NTHREADS;
                const int d = item >> 6;
                const int p = item & 63;
                const int ti = p * 2;
                float q0 = q_s[d * 128 + ti];
                float q1 = q_s[d * 128 + ti + 1];
                float x0 = s_xs[ti * XS_STRIDE + d];
                float x1 = s_xs[(ti + 1) * XS_STRIDE + d];
                float2 stv = make_float2(__fadd_rn(x0, __fsub_rn(q0, x0)),
                                         __fadd_rn(x1, __fsub_rn(q1, x1)));
                float2 qv = make_float2(q0, q1);
                const long long o = obase + (long long)d * TT + t0 + ti;
                *(float2*)(o_st + o) = stv;
                *(float2*)(o_q + o)  = qv;
            }
        }
        __syncthreads();
    }
}

extern "C" void kernel_launch(void* const* d_in, const int* in_sizes, int n_in,
                              void* d_out, int out_size) {
    const float* x   = (const float*)d_in[0];
    const float* emb = (const float*)d_in[1];
    float* out = (float*)d_out;
    (void)in_sizes; (void)n_in; (void)out_size;

    vq_transpose_kernel<<<(KK * DD + 255) / 256, 256>>>(emb);
    cudaFuncSetAttribute(vq_mma_kernel,
                         cudaFuncAttributeMaxDynamicSharedMemorySize, SMEM_TOTAL);
    vq_mma_kernel<<<GRIDX, NTHREADS, SMEM_TOTAL>>>(x, emb, out);
}

// round 15
// speedup vs baseline: 2.1630x; 1.2983x over previous
#include <cuda_runtime.h>
#include <cuda_bf16.h>
#include <cstdint>

// VectorQuantizer via mma.sync (HMMA bf16, split-precision) + exact-margin rescore.
// R15 = R5 screen + coalesced MLP-pipelined warp-per-token rescore via transposed
// codebook in __device__ global. B=32, D=64, T=8192, K=512.

#define BB 32
#define DD 64
#define TT 8192
#define KK 512
#define NTOK (BB * TT)
#define TILE_M 128
#define NTILES (NTOK / TILE_M)      // 2048
#define TILES_PER_B (TT / TILE_M)   // 64
#define NTHREADS 256
#define GRIDX 152
#define ARRSZ ((long long)BB * DD * TT)
#define MARGIN 5e-5f
#define FINF 3.402823466e38f

// bf16 row stride: 72 elems = 144 bytes (conflict-free ldmatrix)
#define ROWS72 72
#define RSTRIDE (ROWS72 * 2)

// smem byte offsets
#define OFF_QN     0
#define OFF_E2     128      // 512 f -> 2176
#define OFF_X2     2176     // 128 f -> 2688
#define OFF_WIN    2688     // 128 i -> 3200
#define OFF_QUE    3200     // 128 i -> 3712
#define OFF_XS     3712     // 128*65*4 = 33280 -> 36992
#define OFF_XH     36992    // 128*144 = 18432 -> 55424
#define OFF_XL     55424    // 18432 -> 73856
#define OFF_QS     OFF_XH   // overlay: 64*128*4 = 32768 <= 36864 (XH+XL)
#define OFF_EH     73856    // 512*144 = 73728 -> 147584
#define OFF_EL     147584   // 73728 -> 221312
#define SMEM_TOTAL 221312
#define XS_STRIDE  65

// transposed f32 codebook: embT[d][k]
__device__ __align__(16) float g_embT[DD * KK];

__global__ void vq_transpose_kernel(const float* __restrict__ emb) {
    const int idx = blockIdx.x * blockDim.x + threadIdx.x;
    if (idx < KK * DD) {
        const int k = idx / DD;
        const int d = idx % DD;
        g_embT[d * KK + k] = emb[idx];
    }
}

__device__ __forceinline__ uint32_t smem_u32(const void* p) {
    uint32_t a;
    asm("{ .reg .u64 t; cvta.to.shared.u64 t, %1; cvt.u32.u64 %0, t; }" : "=r"(a) : "l"(p));
    return a;
}
__device__ __forceinline__ void ldsm_x4(uint32_t& r0, uint32_t& r1, uint32_t& r2, uint32_t& r3,
                                        uint32_t addr) {
    asm volatile("ldmatrix.sync.aligned.m8n8.x4.shared.b16 {%0,%1,%2,%3}, [%4];"
                 : "=r"(r0), "=r"(r1), "=r"(r2), "=r"(r3) : "r"(addr));
}
__device__ __forceinline__ void mma_bf16(float* c, const uint32_t* a, uint32_t b0, uint32_t b1) {
    asm volatile("mma.sync.aligned.m16n8k16.row.col.f32.bf16.bf16.f32 "
                 "{%0,%1,%2,%3}, {%4,%5,%6,%7}, {%8,%9}, {%0,%1,%2,%3};"
                 : "+f"(c[0]), "+f"(c[1]), "+f"(c[2]), "+f"(c[3])
                 : "r"(a[0]), "r"(a[1]), "r"(a[2]), "r"(a[3]), "r"(b0), "r"(b1));
}
__device__ __forceinline__ uint32_t pack_hi2(float v0, float v1, float& r0, float& r1) {
    __nv_bfloat16 h0 = __float2bfloat16_rn(v0);
    __nv_bfloat16 h1 = __float2bfloat16_rn(v1);
    r0 = __fsub_rn(v0, __bfloat162float(h0));
    r1 = __fsub_rn(v1, __bfloat162float(h1));
    return (uint32_t)__bfloat16_as_ushort(h0) | ((uint32_t)__bfloat16_as_ushort(h1) << 16);
}
__device__ __forceinline__ uint32_t pack_lo2(float r0, float r1) {
    __nv_bfloat16 l0 = __float2bfloat16_rn(r0);
    __nv_bfloat16 l1 = __float2bfloat16_rn(r1);
    return (uint32_t)__bfloat16_as_ushort(l0) | ((uint32_t)__bfloat16_as_ushort(l1) << 16);
}
__device__ __forceinline__ void top2(float dd, int k, float& d1, float& d2, int& i1) {
    if (dd < d1) { d2 = d1; d1 = dd; i1 = k; }
    else if (dd < d2) { d2 = dd; }
}

extern __shared__ __align__(1024) char smem[];

__global__ void __launch_bounds__(NTHREADS, 1)
vq_mma_kernel(const float* __restrict__ x,
              const float* __restrict__ emb,
              float* __restrict__ out) {
    const int tid  = threadIdx.x;
    const int wid  = tid >> 5;
    const int lane = tid & 31;
    const uint32_t sb = smem_u32(smem);

    float* s_e2   = (float*)(smem + OFF_E2);
    float* s_x2   = (float*)(smem + OFF_X2);
    int*   s_win  = (int*)(smem + OFF_WIN);
    int*   s_que  = (int*)(smem + OFF_QUE);
    float* s_xs   = (float*)(smem + OFF_XS);
    int*   s_qn   = (int*)(smem + OFF_QN);
    float* q_s    = (float*)(smem + OFF_QS);

    // ---- Prologue: codebook -> exact e2 chain + bf16 split rows [512][72] ----
    for (int r = tid; r < KK; r += NTHREADS) {
        float ev[DD];
        const float4* er = (const float4*)(emb + r * DD);
        #pragma unroll
        for (int g = 0; g < DD / 4; g++) {
            float4 v = er[g];
            ev[g*4+0] = v.x; ev[g*4+1] = v.y; ev[g*4+2] = v.z; ev[g*4+3] = v.w;
        }
        float s = 0.0f;
        #pragma unroll
        for (int d = 0; d < DD; d++) s = __fadd_rn(s, __fmul_rn(ev[d], ev[d]));
        s_e2[r] = s;
        #pragma unroll
        for (int d = 0; d < DD; d += 2) {
            float r0, r1;
            uint32_t hp = pack_hi2(ev[d], ev[d+1], r0, r1);
            uint32_t lp = pack_lo2(r0, r1);
            *(uint32_t*)(smem + OFF_EH + r * RSTRIDE + d * 2) = hp;
            *(uint32_t*)(smem + OFF_EL + r * RSTRIDE + d * 2) = lp;
        }
    }

    float* o_st = out;
    float* o_q  = out + ARRSZ;

    const int lane4 = lane & 3;
    const int laneg = lane >> 2;
    const uint32_t a_off = (uint32_t)((lane & 15) * RSTRIDE + (lane >> 4) * 16);
    const uint32_t b_off = (uint32_t)((((lane & 7) + ((lane >> 4) << 3)) * RSTRIDE) +
                                      (((lane >> 3) & 1) * 16));

    for (int tile = blockIdx.x; tile < NTILES; tile += GRIDX) {
        const int b  = tile / TILES_PER_B;
        const int t0 = (tile % TILES_PER_B) * TILE_M;
        const float* xb = x + (long long)b * DD * TT + t0;
        const long long obase = (long long)b * DD * TT;

        // ---- Phase A: load x, stage f32, exact x2 chain, bf16 split rows ----
        if (tid == 0) *s_qn = 0;
        if (tid < TILE_M) {
            const int tt = tid;
            float xv[DD];
            #pragma unroll
            for (int d = 0; d < DD; d++) xv[d] = xb[(long long)d * TT + tt];
            float s = 0.0f;
            #pragma unroll
            for (int d = 0; d < DD; d++) {
                s_xs[tt * XS_STRIDE + d] = xv[d];
                s = __fadd_rn(s, __fmul_rn(xv[d], xv[d]));
            }
            s_x2[tt] = s;
            #pragma unroll
            for (int d = 0; d < DD; d += 2) {
                float r0, r1;
                uint32_t hp = pack_hi2(xv[d], xv[d+1], r0, r1);
                uint32_t lp = pack_lo2(r0, r1);
                *(uint32_t*)(smem + OFF_XH + tt * RSTRIDE + d * 2) = hp;
                *(uint32_t*)(smem + OFF_XL + tt * RSTRIDE + d * 2) = lp;
            }
        }
        __syncthreads();

        // ---- Phase B: screen. warp w: tokens [16w,16w+16), all 512 codes ----
        {
            const int m0 = wid * 16;
            uint32_t ah[4][4], al[4][4];
            const uint32_t abh = sb + OFF_XH + m0 * RSTRIDE + a_off;
            const uint32_t abl = sb + OFF_XL + m0 * RSTRIDE + a_off;
            #pragma unroll
            for (int s = 0; s < 4; s++) {
                ldsm_x4(ah[s][0], ah[s][1], ah[s][2], ah[s][3], abh + s * 32);
                ldsm_x4(al[s][0], al[s][1], al[s][2], al[s][3], abl + s * 32);
            }

            float d1a = FINF, d2a = FINF, d1b = FINF, d2b = FINF;
            int   i1a = 0, i1b = 0;
            const uint32_t bbh = sb + OFF_EH + b_off;
            const uint32_t bbl = sb + OFF_EL + b_off;

            for (int c = 0; c < 8; c++) {
                const int n0 = c * 64;
                #pragma unroll
                for (int p = 0; p < 4; p++) {
                    float a0[8], a1[8];
                    #pragma unroll
                    for (int j = 0; j < 8; j++) { a0[j] = 0.f; a1[j] = 0.f; }
                    const uint32_t bth = bbh + (uint32_t)((n0 + 16 * p) * RSTRIDE);
                    const uint32_t btl = bbl + (uint32_t)((n0 + 16 * p) * RSTRIDE);
                    #pragma unroll
                    for (int s = 0; s < 4; s++) {
                        uint32_t h0, h1, h2, h3, l0, l1, l2, l3;
                        ldsm_x4(h0, h1, h2, h3, bth + s * 32);
                        ldsm_x4(l0, l1, l2, l3, btl + s * 32);
                        mma_bf16(a0,     ah[s], h0, h1);   // hh
                        mma_bf16(a0 + 4, ah[s], h2, h3);
                        mma_bf16(a1,     ah[s], l0, l1);   // hl
                        mma_bf16(a1 + 4, ah[s], l2, l3);
                        mma_bf16(a1,     al[s], h0, h1);   // lh
                        mma_bf16(a1 + 4, al[s], h2, h3);
                    }
                    const int cb0 = n0 + 16 * p + 2 * lane4;
                    const int cb1 = cb0 + 8;
                    const float e00 = s_e2[cb0], e01 = s_e2[cb0 + 1];
                    const float e10 = s_e2[cb1], e11 = s_e2[cb1 + 1];
                    float v;
                    v = __fadd_rn(a0[0], a1[0]);
                    top2(fmaf(-2.0f, v, e00), cb0,     d1a, d2a, i1a);
                    v = __fadd_rn(a0[1], a1[1]);
                    top2(fmaf(-2.0f, v, e01), cb0 + 1, d1a, d2a, i1a);
                    v = __fadd_rn(a0[2], a1[2]);
                    top2(fmaf(-2.0f, v, e00), cb0,     d1b, d2b, i1b);
                    v = __fadd_rn(a0[3], a1[3]);
                    top2(fmaf(-2.0f, v, e01), cb0 + 1, d1b, d2b, i1b);
                    v = __fadd_rn(a0[4], a1[4]);
                    top2(fmaf(-2.0f, v, e10), cb1,     d1a, d2a, i1a);
                    v = __fadd_rn(a0[5], a1[5]);
                    top2(fmaf(-2.0f, v, e11), cb1 + 1, d1a, d2a, i1a);
                    v = __fadd_rn(a0[6], a1[6]);
                    top2(fmaf(-2.0f, v, e10), cb1,     d1b, d2b, i1b);
                    v = __fadd_rn(a0[7], a1[7]);
                    top2(fmaf(-2.0f, v, e11), cb1 + 1, d1b, d2b, i1b);
                }
            }

            // quad reduce (lanes xor 1, 2) lexicographic (d, k)
            #pragma unroll
            for (int m = 1; m <= 2; m <<= 1) {
                float od = __shfl_xor_sync(0xffffffffu, d1a, m);
                int   oi = __shfl_xor_sync(0xffffffffu, i1a, m);
                float o2 = __shfl_xor_sync(0xffffffffu, d2a, m);
                bool take = (od < d1a) || (od == d1a && oi < i1a);
                float nd2 = take ? fminf(d1a, o2) : fminf(d2a, od);
                if (take) { d1a = od; i1a = oi; }
                d2a = nd2;
                od = __shfl_xor_sync(0xffffffffu, d1b, m);
                oi = __shfl_xor_sync(0xffffffffu, i1b, m);
                o2 = __shfl_xor_sync(0xffffffffu, d2b, m);
                take = (od < d1b) || (od == d1b && oi < i1b);
                nd2 = take ? fminf(d1b, o2) : fminf(d2b, od);
                if (take) { d1b = od; i1b = oi; }
                d2b = nd2;
            }
            if (lane4 == 0) {
                const int r0 = m0 + laneg, r1 = r0 + 8;
                s_win[r0] = i1a;
                if (!(d2a - d1a > MARGIN)) { int q = atomicAdd(s_qn, 1); s_que[q] = r0; }
                s_win[r1] = i1b;
                if (!(d2b - d1b > MARGIN)) { int q = atomicAdd(s_qn, 1); s_que[q] = r1; }
            }
        }
        __syncthreads();

        // ---- Phase E: warp-per-token exact rescore, coalesced + MLP-pipelined ----
        // lane owns codes {q*128 + lane*4 + jj}; per-code fmaf chain ascending d
        // (identical to reference chain); lexicographic (d,k) reduce.
        {
            const int nq = *s_qn;
            for (int j = wid; j < nq; j += 8) {
                const int tt = s_que[j];
                const float x2t = s_x2[tt];
                float ps[16];
                #pragma unroll
                for (int i = 0; i < 16; i++) ps[i] = 0.0f;
                #pragma unroll 1
                for (int d0 = 0; d0 < DD; d0 += 4) {
                    // 16 independent coalesced LDG.128 in flight per group
                    float4 v[4][4];
                    float xd[4];
                    #pragma unroll
                    for (int dd = 0; dd < 4; dd++) {
                        xd[dd] = s_xs[tt * XS_STRIDE + d0 + dd];
                        const float4* row = (const float4*)(g_embT + (d0 + dd) * KK);
                        #pragma unroll
                        for (int q = 0; q < 4; q++)
                            v[dd][q] = __ldg(row + (q * 32 + lane));
                    }
                    #pragma unroll
                    for (int dd = 0; dd < 4; dd++) {
                        #pragma unroll
                        for (int q = 0; q < 4; q++) {
                            ps[q*4+0] = fmaf(xd[dd], v[dd][q].x, ps[q*4+0]);
                            ps[q*4+1] = fmaf(xd[dd], v[dd][q].y, ps[q*4+1]);
                            ps[q*4+2] = fmaf(xd[dd], v[dd][q].z, ps[q*4+2]);
                            ps[q*4+3] = fmaf(xd[dd], v[dd][q].w, ps[q*4+3]);
                        }
                    }
                }
                float bd = FINF; int bk = 0;
                #pragma unroll
                for (int q = 0; q < 4; q++) {
                    #pragma unroll
                    for (int jj = 0; jj < 4; jj++) {
                        const int k = q * 128 + lane * 4 + jj;   // ascending per lane
                        float dA = __fadd_rn(__fsub_rn(x2t, 2.0f * ps[q*4+jj]), s_e2[k]);
                        if (dA < bd) { bd = dA; bk = k; }
                    }
                }
                #pragma unroll
                for (int off = 16; off; off >>= 1) {
                    float od = __shfl_down_sync(0xFFFFFFFFu, bd, off);
                    int   ok = __shfl_down_sync(0xFFFFFFFFu, bk, off);
                    if (od < bd || (od == bd && ok < bk)) { bd = od; bk = ok; }
                }
                if (lane == 0) s_win[tt] = bk;
            }
        }
        __syncthreads();

        // ---- Phase F: gather q rows (overlay XH/XL) then coalesced writes ----
        if (tid < TILE_M) {
            const int tt = tid;
            const int k = s_win[tt];
            const float4* er = (const float4*)(emb + k * DD);
            #pragma unroll
            for (int g = 0; g < DD / 4; g++) {
                float4 v = __ldg(er + g);
                q_s[(g*4+0) * 128 + tt] = v.x;
                q_s[(g*4+1) * 128 + tt] = v.y;
                q_s[(g*4+2) * 128 + tt] = v.z;
                q_s[(g*4+3) * 128 + tt] = v.w;
            }
        }
        __syncthreads();
        {
            #pragma unroll
            for (int it = 0; it < (64 * 64) / NTHREADS; it++) {
                const int item = tid + it * NTHREADS;
                const int d = item >> 6;
                const int p = item & 63;
                const int ti = p * 2;
                float q0 = q_s[d * 128 + ti];
                float q1 = q_s[d * 128 + ti + 1];
                float x0 = s_xs[ti * XS_STRIDE + d];
                float x1 = s_xs[(ti + 1) * XS_STRIDE + d];
                float2 stv = make_float2(__fadd_rn(x0, __fsub_rn(q0, x0)),
                                         __fadd_rn(x1, __fsub_rn(q1, x1)));
                float2 qv = make_float2(q0, q1);
                const long long o = obase + (long long)d * TT + t0 + ti;
                *(float2*)(o_st + o) = stv;
                *(float2*)(o_q + o)  = qv;
            }
        }
        __syncthreads();
    }
}

extern "C" void kernel_launch(void* const* d_in, const int* in_sizes, int n_in,
                              void* d_out, int out_size) {
    const float* x   = (const float*)d_in[0];
    const float* emb = (const float*)d_in[1];
    float* out = (float*)d_out;
    (void)in_sizes; (void)n_in; (void)out_size;

    vq_transpose_kernel<<<(KK * DD + 255) / 256, 256>>>(emb);
    cudaFuncSetAttribute(vq_mma_kernel,
                         cudaFuncAttributeMaxDynamicSharedMemorySize, SMEM_TOTAL);
    vq_mma_kernel<<<GRIDX, NTHREADS, SMEM_TOTAL>>>(x, emb, out);
}

// round 16
// speedup vs baseline: 2.6448x; 1.2227x over previous
#include <cuda_runtime.h>
#include <cuda_fp16.h>
#include <cstdint>

// VectorQuantizer: x-split FP16 2-product mma.sync screen (e pre-scaled x1024,
// xl pre-scaled x2048) + provable-margin exact rescore (coalesced, warp-per-token).
// 512 threads, TILE_M=256. B=32, D=64, T=8192, K=512.

#define BB 32
#define DD 64
#define TT 8192
#define KK 512
#define TILE_M 256
#define NTILES 1024
#define TILES_PER_B 32
#define NTHREADS 512
#define GRIDX 152
#define ARRSZ ((long long)BB * DD * TT)
#define MARGIN 1.5e-4f
#define FINF 3.402823466e38f

#define RSTRIDE 144                 // 72 fp16/row (conflict-free ldmatrix)
#define C1F (-0.001953125f)         // -2/1024  (xh * e1024)
#define C2F (-9.5367431640625e-7f)  // -2/2^21  (xl2048 * e1024)
#define XS_STRIDE 65

// smem byte offsets
#define OFF_QN   0
#define OFF_E2   128       // 512 f -> 2176
#define OFF_X2   2176      // 256 f -> 3200
#define OFF_WIN  3200      // 256 i -> 4224
#define OFF_QUE  4224      // 256 i -> 5248
#define OFF_XS   5376      // 256*65*4 = 66560 -> 71936
#define OFF_XH   71936     // 256*144 = 36864 -> 108800
#define OFF_XL   108800    // 36864 -> 145664
#define OFF_QS   OFF_XH    // overlay: 64*256*4 = 65536 <= 73728 (XH+XL)
#define OFF_EH   145664    // 512*144 = 73728 -> 219392
#define SMEM_TOTAL 219392

// transposed f32 codebook: embT[d][k]
__device__ __align__(16) float g_embT[DD * KK];

__global__ void vq_transpose_kernel(const float* __restrict__ emb) {
    const int idx = blockIdx.x * blockDim.x + threadIdx.x;
    if (idx < KK * DD) {
        const int k = idx / DD;
        const int d = idx % DD;
        g_embT[d * KK + k] = emb[idx];
    }
}

__device__ __forceinline__ uint32_t smem_u32(const void* p) {
    uint32_t a;
    asm("{ .reg .u64 t; cvta.to.shared.u64 t, %1; cvt.u32.u64 %0, t; }" : "=r"(a) : "l"(p));
    return a;
}
__device__ __forceinline__ void ldsm_x4(uint32_t& r0, uint32_t& r1, uint32_t& r2, uint32_t& r3,
                                        uint32_t addr) {
    asm volatile("ldmatrix.sync.aligned.m8n8.x4.shared.b16 {%0,%1,%2,%3}, [%4];"
                 : "=r"(r0), "=r"(r1), "=r"(r2), "=r"(r3) : "r"(addr));
}
__device__ __forceinline__ void mma_f16(float* c, const uint32_t* a, uint32_t b0, uint32_t b1) {
    asm volatile("mma.sync.aligned.m16n8k16.row.col.f32.f16.f16.f32 "
                 "{%0,%1,%2,%3}, {%4,%5,%6,%7}, {%8,%9}, {%0,%1,%2,%3};"
                 : "+f"(c[0]), "+f"(c[1]), "+f"(c[2]), "+f"(c[3])
                 : "r"(a[0]), "r"(a[1]), "r"(a[2]), "r"(a[3]), "r"(b0), "r"(b1));
}
__device__ __forceinline__ uint32_t pack_h2(float lo, float hi) {
    __half2 h = __floats2half2_rn(lo, hi);
    return *reinterpret_cast<uint32_t*>(&h);
}
__device__ __forceinline__ void top2(float dd, int k, float& d1, float& d2, int& i1) {
    if (dd < d1) { d2 = d1; d1 = dd; i1 = k; }
    else if (dd < d2) { d2 = dd; }
}

extern __shared__ __align__(1024) char smem[];

__global__ void __launch_bounds__(NTHREADS, 1)
vq_xs_kernel(const float* __restrict__ x,
             const float* __restrict__ emb,
             float* __restrict__ out) {
    const int tid  = threadIdx.x;
    const int wid  = tid >> 5;
    const int lane = tid & 31;
    const uint32_t sb = smem_u32(smem);

    float* s_e2  = (float*)(smem + OFF_E2);
    float* s_x2  = (float*)(smem + OFF_X2);
    int*   s_win = (int*)(smem + OFF_WIN);
    int*   s_que = (int*)(smem + OFF_QUE);
    float* s_xs  = (float*)(smem + OFF_XS);
    int*   s_qn  = (int*)(smem + OFF_QN);
    float* q_s   = (float*)(smem + OFF_QS);

    // ---- Prologue: codebook -> exact e2 chain + fp16 rows (e*1024) ----
    for (int r = tid; r < KK; r += NTHREADS) {
        float ev[DD];
        const float4* er = (const float4*)(emb + r * DD);
        #pragma unroll
        for (int g = 0; g < DD / 4; g++) {
            float4 v = er[g];
            ev[g*4+0] = v.x; ev[g*4+1] = v.y; ev[g*4+2] = v.z; ev[g*4+3] = v.w;
        }
        float s = 0.0f;
        #pragma unroll
        for (int d = 0; d < DD; d++) s = __fadd_rn(s, __fmul_rn(ev[d], ev[d]));
        s_e2[r] = s;
        #pragma unroll
        for (int d = 0; d < DD; d += 2)
            *(uint32_t*)(smem + OFF_EH + r * RSTRIDE + d * 2) =
                pack_h2(ev[d] * 1024.0f, ev[d+1] * 1024.0f);
    }

    float* o_st = out;
    float* o_q  = out + ARRSZ;

    const int lane4 = lane & 3;
    const int laneg = lane >> 2;
    const uint32_t a_off = (uint32_t)((lane & 15) * RSTRIDE + (lane >> 4) * 16);
    const uint32_t b_off = (uint32_t)((((lane & 7) + ((lane >> 4) << 3)) * RSTRIDE) +
                                      (((lane >> 3) & 1) * 16));

    for (int tile = blockIdx.x; tile < NTILES; tile += GRIDX) {
        const int b  = tile / TILES_PER_B;
        const int t0 = (tile % TILES_PER_B) * TILE_M;
        const float* xb = x + (long long)b * DD * TT + t0;
        const long long obase = (long long)b * DD * TT;

        // ---- Phase A: x load (threads 0..255), exact x2 chain, fp16 split ----
        if (tid == 0) *s_qn = 0;
        if (tid < TILE_M) {
            const int tt = tid;
            float xv[DD];
            #pragma unroll
            for (int d = 0; d < DD; d++) xv[d] = xb[(long long)d * TT + tt];
            float s = 0.0f;
            #pragma unroll
            for (int d = 0; d < DD; d++) {
                s_xs[tt * XS_STRIDE + d] = xv[d];
                s = __fadd_rn(s, __fmul_rn(xv[d], xv[d]));
            }
            s_x2[tt] = s;
            #pragma unroll
            for (int d = 0; d < DD; d += 2) {
                __half h0 = __float2half_rn(xv[d]);
                __half h1 = __float2half_rn(xv[d+1]);
                float r0 = __fsub_rn(xv[d],   __half2float(h0)) * 2048.0f;
                float r1 = __fsub_rn(xv[d+1], __half2float(h1)) * 2048.0f;
                uint32_t hp = (uint32_t)__half_as_ushort(h0) |
                              ((uint32_t)__half_as_ushort(h1) << 16);
                *(uint32_t*)(smem + OFF_XH + tt * RSTRIDE + d * 2) = hp;
                *(uint32_t*)(smem + OFF_XL + tt * RSTRIDE + d * 2) = pack_h2(r0, r1);
            }
        }
        __syncthreads();

        // ---- Phase B: screen. warp w: tokens [16w,16w+16), ALL 512 codes ----
        {
            const int m0 = wid * 16;
            uint32_t ah[4][4], al[4][4];
            const uint32_t abh = sb + OFF_XH + m0 * RSTRIDE + a_off;
            const uint32_t abl = sb + OFF_XL + m0 * RSTRIDE + a_off;
            #pragma unroll
            for (int s = 0; s < 4; s++) {
                ldsm_x4(ah[s][0], ah[s][1], ah[s][2], ah[s][3], abh + s * 32);
                ldsm_x4(al[s][0], al[s][1], al[s][2], al[s][3], abl + s * 32);
            }

            float d1a = FINF, d2a = FINF, d1b = FINF, d2b = FINF;
            int   i1a = 0, i1b = 0;
            const uint32_t bbh = sb + OFF_EH + b_off;

            for (int c = 0; c < 8; c++) {
                const int n0 = c * 64;
                #pragma unroll
                for (int p = 0; p < 4; p++) {
                    float aH[8], aL[8];
                    #pragma unroll
                    for (int j = 0; j < 8; j++) { aH[j] = 0.f; aL[j] = 0.f; }
                    const uint32_t bt = bbh + (uint32_t)((n0 + 16 * p) * RSTRIDE);
                    #pragma unroll
                    for (int s = 0; s < 4; s++) {
                        uint32_t b0, b1, b2, b3;
                        ldsm_x4(b0, b1, b2, b3, bt + s * 32);
                        mma_f16(aH,     ah[s], b0, b1);
                        mma_f16(aH + 4, ah[s], b2, b3);
                        mma_f16(aL,     al[s], b0, b1);
                        mma_f16(aL + 4, al[s], b2, b3);
                    }
                    // dist(screen) = e2 - 2*xh.e - 2*xl.e
                    const int cb0 = n0 + 16 * p + 2 * lane4;
                    const int cb1 = cb0 + 8;
                    const float e00 = s_e2[cb0], e01 = s_e2[cb0 + 1];
                    const float e10 = s_e2[cb1], e11 = s_e2[cb1 + 1];
                    float dd;
                    dd = fmaf(C1F, aH[0], fmaf(C2F, aL[0], e00));
                    top2(dd, cb0,     d1a, d2a, i1a);
                    dd = fmaf(C1F, aH[1], fmaf(C2F, aL[1], e01));
                    top2(dd, cb0 + 1, d1a, d2a, i1a);
                    dd = fmaf(C1F, aH[2], fmaf(C2F, aL[2], e00));
                    top2(dd, cb0,     d1b, d2b, i1b);
                    dd = fmaf(C1F, aH[3], fmaf(C2F, aL[3], e01));
                    top2(dd, cb0 + 1, d1b, d2b, i1b);
                    dd = fmaf(C1F, aH[4], fmaf(C2F, aL[4], e10));
                    top2(dd, cb1,     d1a, d2a, i1a);
                    dd = fmaf(C1F, aH[5], fmaf(C2F, aL[5], e11));
                    top2(dd, cb1 + 1, d1a, d2a, i1a);
                    dd = fmaf(C1F, aH[6], fmaf(C2F, aL[6], e10));
                    top2(dd, cb1,     d1b, d2b, i1b);
                    dd = fmaf(C1F, aH[7], fmaf(C2F, aL[7], e11));
                    top2(dd, cb1 + 1, d1b, d2b, i1b);
                }
            }

            // quad reduce (lanes xor 1, 2) lexicographic (d, k)
            #pragma unroll
            for (int m = 1; m <= 2; m <<= 1) {
                float od = __shfl_xor_sync(0xffffffffu, d1a, m);
                int   oi = __shfl_xor_sync(0xffffffffu, i1a, m);
                float o2 = __shfl_xor_sync(0xffffffffu, d2a, m);
                bool take = (od < d1a) || (od == d1a && oi < i1a);
                float nd2 = take ? fminf(d1a, o2) : fminf(d2a, od);
                if (take) { d1a = od; i1a = oi; }
                d2a = nd2;
                od = __shfl_xor_sync(0xffffffffu, d1b, m);
                oi = __shfl_xor_sync(0xffffffffu, i1b, m);
                o2 = __shfl_xor_sync(0xffffffffu, d2b, m);
                take = (od < d1b) || (od == d1b && oi < i1b);
                nd2 = take ? fminf(d1b, o2) : fminf(d2b, od);
                if (take) { d1b = od; i1b = oi; }
                d2b = nd2;
            }
            if (lane4 == 0) {
                const int r0 = m0 + laneg, r1 = r0 + 8;
                s_win[r0] = i1a;
                if (!(d2a - d1a > MARGIN)) { int q = atomicAdd(s_qn, 1); s_que[q] = r0; }
                s_win[r1] = i1b;
                if (!(d2b - d1b > MARGIN)) { int q = atomicAdd(s_qn, 1); s_que[q] = r1; }
            }
        }
        __syncthreads();

        // ---- Phase E: warp-per-token exact rescore, coalesced + pipelined ----
        {
            const int nq = *s_qn;
            for (int j = wid; j < nq; j += 16) {
                const int tt = s_que[j];
                const float x2t = s_x2[tt];
                float ps[16];
                #pragma unroll
                for (int i = 0; i < 16; i++) ps[i] = 0.0f;
                #pragma unroll 1
                for (int d0 = 0; d0 < DD; d0 += 4) {
                    float4 v[4][4];
                    float xd[4];
                    #pragma unroll
                    for (int dd = 0; dd < 4; dd++) {
                        xd[dd] = s_xs[tt * XS_STRIDE + d0 + dd];
                        const float4* row = (const float4*)(g_embT + (d0 + dd) * KK);
                        #pragma unroll
                        for (int q = 0; q < 4; q++)
                            v[dd][q] = __ldg(row + (q * 32 + lane));
                    }
                    #pragma unroll
                    for (int dd = 0; dd < 4; dd++) {
                        #pragma unroll
                        for (int q = 0; q < 4; q++) {
                            ps[q*4+0] = fmaf(xd[dd], v[dd][q].x, ps[q*4+0]);
                            ps[q*4+1] = fmaf(xd[dd], v[dd][q].y, ps[q*4+1]);
                            ps[q*4+2] = fmaf(xd[dd], v[dd][q].z, ps[q*4+2]);
                            ps[q*4+3] = fmaf(xd[dd], v[dd][q].w, ps[q*4+3]);
                        }
                    }
                }
                float bd = FINF; int bk = 0;
                #pragma unroll
                for (int q = 0; q < 4; q++) {
                    #pragma unroll
                    for (int jj = 0; jj < 4; jj++) {
                        const int k = q * 128 + lane * 4 + jj;
                        float dA = __fadd_rn(__fsub_rn(x2t, 2.0f * ps[q*4+jj]), s_e2[k]);
                        if (dA < bd) { bd = dA; bk = k; }
                    }
                }
                #pragma unroll
                for (int off = 16; off; off >>= 1) {
                    float od = __shfl_down_sync(0xFFFFFFFFu, bd, off);
                    int   ok = __shfl_down_sync(0xFFFFFFFFu, bk, off);
                    if (od < bd || (od == bd && ok < bk)) { bd = od; bk = ok; }
                }
                if (lane == 0) s_win[tt] = bk;
            }
        }
        __syncthreads();

        // ---- Phase F: gather q rows (overlay XH/XL) then coalesced writes ----
        if (tid < TILE_M) {
            const int tt = tid;
            const int k = s_win[tt];
            const float4* er = (const float4*)(emb + k * DD);
            #pragma unroll
            for (int g = 0; g < DD / 4; g++) {
                float4 v = __ldg(er + g);
                q_s[(g*4+0) * TILE_M + tt] = v.x;
                q_s[(g*4+1) * TILE_M + tt] = v.y;
                q_s[(g*4+2) * TILE_M + tt] = v.z;
                q_s[(g*4+3) * TILE_M + tt] = v.w;
            }
        }
        __syncthreads();
        {
            #pragma unroll
            for (int it = 0; it < (DD * TILE_M / 2) / NTHREADS; it++) {
                const int item = tid + it * NTHREADS;
                const int d = item >> 7;          // 0..63
                const int p = item & 127;         // 0..127
                const int ti = p * 2;
                float q0 = q_s[d * TILE_M + ti];
                float q1 = q_s[d * TILE_M + ti + 1];
                float x0 = s_xs[ti * XS_STRIDE + d];
                float x1 = s_xs[(ti + 1) * XS_STRIDE + d];
                float2 stv = make_float2(__fadd_rn(x0, __fsub_rn(q0, x0)),
                                         __fadd_rn(x1, __fsub_rn(q1, x1)));
                float2 qv = make_float2(q0, q1);
                const long long o = obase + (long long)d * TT + t0 + ti;
                *(float2*)(o_st + o) = stv;
                *(float2*)(o_q + o)  = qv;
            }
        }
        __syncthreads();
    }
}

extern "C" void kernel_launch(void* const* d_in, const int* in_sizes, int n_in,
                              void* d_out, int out_size) {
    const float* x   = (const float*)d_in[0];
    const float* emb = (const float*)d_in[1];
    float* out = (float*)d_out;
    (void)in_sizes; (void)n_in; (void)out_size;

    vq_transpose_kernel<<<(KK * DD + 255) / 256, 256>>>(emb);
    cudaFuncSetAttribute(vq_xs_kernel,
                         cudaFuncAttributeMaxDynamicSharedMemorySize, SMEM_TOTAL);
    vq_xs_kernel<<<GRIDX, NTHREADS, SMEM_TOTAL>>>(x, emb, out);
}